// round 13
// baseline (speedup 1.0000x reference)
#include <cuda_runtime.h>
#include <cstdint>

// NCA grow step — fire-sparsity compaction + tensor-core (mma.sync tf32) layer 1.
//
//  zero:  reset compaction counter.
//  prep:  fire = rand_mask <= 0.5; non-fired: out = x (+alpha); fired -> g_list.
//  mlp:   persistent 296x128. Per warp: 32 compacted pixels.
//         perceive -> ybuf (SMEM, [64k][32pix] padded)
//         layer1 on HMMA: D[32pix,64h-chunk] = Y[32,64] x W1^T, m16n8k8 tf32,
//           exact 3-term split (yh*wh + yl*wh + yh*wl), fp32 accum, 2 chunks
//         relu+b1 -> hbuf -> scalar f32x2 layer2 partials -> epilogue.
//  life:  zero non-living pixels (maxpool3 pre/post alpha).
//
// (tcgen05 unusable: harness targets compute_100; mma.sync tf32 is sm_80+.)

typedef unsigned long long ULL;

#define HW 65536

__device__ float g_alpha[16 * HW];
__device__ int   g_list[16 * HW];
__device__ int   g_count;

__device__ __forceinline__ ULL pack2(float lo, float hi) {
    ULL r; asm("mov.b64 %0, {%1, %2};" : "=l"(r) : "f"(lo), "f"(hi)); return r;
}
__device__ __forceinline__ void unpack2(float& lo, float& hi, ULL v) {
    asm("mov.b64 {%0, %1}, %2;" : "=f"(lo), "=f"(hi) : "l"(v));
}
__device__ __forceinline__ ULL fma2(ULL a, ULL b, ULL c) {
    ULL d; asm("fma.rn.f32x2 %0, %1, %2, %3;" : "=l"(d) : "l"(a), "l"(b), "l"(c)); return d;
}
__device__ __forceinline__ void pf_l1(const void* p) {
    asm volatile("prefetch.global.L1 [%0];" :: "l"(p));
}
// exact tf32 split: v = hi + lo (+ tiny), hi/lo returned as b32 tf32 patterns
__device__ __forceinline__ void tf32_split(float v, uint32_t& hi, uint32_t& lo) {
    asm("cvt.rna.tf32.f32 %0, %1;" : "=r"(hi) : "f"(v));
    float r = v - __uint_as_float(hi);
    asm("cvt.rna.tf32.f32 %0, %1;" : "=r"(lo) : "f"(r));
}
__device__ __forceinline__ void mma_16n8k8(float* d, const uint32_t* a, uint32_t b0, uint32_t b1) {
    asm volatile(
        "mma.sync.aligned.m16n8k8.row.col.f32.tf32.tf32.f32 "
        "{%0,%1,%2,%3}, {%4,%5,%6,%7}, {%8,%9}, {%0,%1,%2,%3};"
        : "+f"(d[0]), "+f"(d[1]), "+f"(d[2]), "+f"(d[3])
        : "r"(a[0]), "r"(a[1]), "r"(a[2]), "r"(a[3]), "r"(b0), "r"(b1));
}

__global__ void nca_zero_kernel() { g_count = 0; }

__global__ void __launch_bounds__(256) nca_prep_kernel(
    const float* __restrict__ x, const float* __restrict__ rmask,
    float* __restrict__ out)
{
    const int w = threadIdx.x;
    const int h = blockIdx.x;
    const int b = blockIdx.y;
    const int pid = h * 256 + w;
    const int lane = w & 31;

    const bool fire = __ldg(rmask + (size_t)b * HW + pid) <= 0.5f;
    unsigned m = __ballot_sync(0xffffffffu, fire);
    int base = 0;
    if (lane == 0) base = atomicAdd(&g_count, __popc(m));
    base = __shfl_sync(0xffffffffu, base, 0);
    if (fire) {
        g_list[base + __popc(m & ((1u << lane) - 1u))] = b * HW + pid;
    } else {
#pragma unroll
        for (int c = 0; c < 16; c++) {
            float v = __ldg(x + (size_t)(b * 16 + c) * HW + pid);
            out[(size_t)(b * 16 + c) * HW + pid] = v;
            if (c == 3) g_alpha[(size_t)b * HW + pid] = v;
        }
    }
}

#define MLP_BLOCKS 296
#define MLP_THREADS 128
// dynamic smem layout (bytes):
//   w1s   [128][68] f32    @0        34816
//   ybuf  [4][64][36] f32  @34816    36864
//   hbuf  [4][32][68] f32  @71680    34816
//   w2ts  [1024] ULL       @106496    8192
//   b1s   [128] f32        @114688     512
#define SMEM_TOTAL 115200

__global__ void __launch_bounds__(MLP_THREADS) nca_mlp_kernel(
    const float* __restrict__ x,
    const float* __restrict__ w1, const float* __restrict__ b1,
    const float* __restrict__ w2, float* __restrict__ out)
{
    extern __shared__ __align__(16) char smem[];
    float* w1s  = (float*)smem;                 // [128][68]
    float* ybuf = (float*)(smem + 34816);       // [4][64][36]
    float* hbuf = (float*)(smem + 71680);       // [4][32][68]
    ULL*   w2ts = (ULL*)(smem + 106496);        // [1024]
    float* b1s  = (float*)(smem + 114688);      // [128]

    const int tid = threadIdx.x;
    const int lane = tid & 31;
    const int wid = tid >> 5;

    // stage weights
    for (int i = tid; i < 128 * 64; i += MLP_THREADS)
        w1s[(i >> 6) * 68 + (i & 63)] = w1[i];
    for (int i = tid; i < 1024; i += MLP_THREADS) {
        int o = i >> 3, j = i & 7;
        w2ts[i] = pack2(w2[(2 * j) * 128 + o], w2[(2 * j + 1) * 128 + o]);
    }
    if (tid < 128) b1s[tid] = b1[tid];
    __syncthreads();

    const int count = g_count;
    if (count == 0) return;

    float* yb = ybuf + wid * 64 * 36;
    float* hb = hbuf + wid * 32 * 68;

    const int gwarp = blockIdx.x * 4 + wid;
    const int wstride = MLP_BLOCKS * 4 * 32;

    for (int base = gwarp * 32; base < count; base += wstride) {
        int idx = base + lane;
        if (idx >= count) idx = count - 1;   // tail: duplicate last (same value written)
        const int p = __ldg(&g_list[idx]);
        const int b = p >> 16;
        const int pid = p & 0xFFFF;
        const int h = pid >> 8;
        const int w = pid & 255;
        const bool hm = h > 0, hp = h < 255, wm = w > 0, wp = w < 255;

        // ---- perceive -> ybuf[k][lane], keep centers for epilogue ----
        float cen[16];
#pragma unroll
        for (int c = 0; c < 16; c++) {
            const float* xc = x + (size_t)(b * 16 + c) * HW + pid;
            float v00 = (hm && wm) ? __ldg(xc - 257) : 0.f;
            float v01 = hm         ? __ldg(xc - 256) : 0.f;
            float v02 = (hm && wp) ? __ldg(xc - 255) : 0.f;
            float v10 = wm         ? __ldg(xc - 1)   : 0.f;
            float v11 =              __ldg(xc);
            float v12 = wp         ? __ldg(xc + 1)   : 0.f;
            float v20 = (hp && wm) ? __ldg(xc + 255) : 0.f;
            float v21 = hp         ? __ldg(xc + 256) : 0.f;
            float v22 = (hp && wp) ? __ldg(xc + 257) : 0.f;
            float sx  = ((v02 - v00) + 2.f * (v12 - v10) + (v22 - v20)) * 0.125f;
            float sy  = ((v20 - v00) + 2.f * (v21 - v01) + (v22 - v02)) * 0.125f;
            float lap = v01 + v10 + v12 + v21 - 4.f * v11;
            cen[c] = v11;
            yb[(4 * c + 0) * 36 + lane] = v11;
            yb[(4 * c + 1) * 36 + lane] = sx;
            yb[(4 * c + 2) * 36 + lane] = sy;
            yb[(4 * c + 3) * 36 + lane] = lap;
        }

        // prefetch next iteration's stencil rows
        {
            const int nidx = base + wstride + lane;
            if (nidx < count) {
                const int pn = __ldg(&g_list[nidx]);
                const int npid = pn & 0xFFFF;
                const float* xb = x + (size_t)(pn >> 16) * 16 * HW + npid;
                const int up = (npid >= 256) ? -256 : 0;
                const int dn = (npid < HW - 256) ? 256 : 0;
#pragma unroll
                for (int c = 0; c < 16; c++) {
                    const float* r = xb + (size_t)c * HW;
                    pf_l1(r + up); pf_l1(r); pf_l1(r + dn);
                }
            }
        }
        __syncwarp();

        ULL dx2[8];
#pragma unroll
        for (int j = 0; j < 8; j++) dx2[j] = 0ULL;

        const int g4 = lane >> 2;       // 0..7
        const int t4 = lane & 3;        // 0..3

        // ---- two h-chunks of 64 ----
#pragma unroll
        for (int hc = 0; hc < 128; hc += 64) {
            float acc[2][8][4];
#pragma unroll
            for (int m = 0; m < 2; m++)
#pragma unroll
                for (int n = 0; n < 8; n++)
#pragma unroll
                    for (int q = 0; q < 4; q++) acc[m][n][q] = 0.f;

#pragma unroll
            for (int kt = 0; kt < 8; kt++) {
                const int k0 = kt * 8 + t4;
                // A fragments (y) for m-tiles 0,1, split hi/lo
                uint32_t ahi[2][4], alo[2][4];
#pragma unroll
                for (int m = 0; m < 2; m++) {
                    const int p0 = g4 + 16 * m;
                    tf32_split(yb[k0 * 36 + p0],           ahi[m][0], alo[m][0]);
                    tf32_split(yb[k0 * 36 + p0 + 8],       ahi[m][1], alo[m][1]);
                    tf32_split(yb[(k0 + 4) * 36 + p0],     ahi[m][2], alo[m][2]);
                    tf32_split(yb[(k0 + 4) * 36 + p0 + 8], ahi[m][3], alo[m][3]);
                }
#pragma unroll
                for (int nt = 0; nt < 8; nt++) {
                    const int hrow = hc + nt * 8 + g4;
                    uint32_t bh0, bl0, bh1, bl1;
                    tf32_split(w1s[hrow * 68 + k0],     bh0, bl0);
                    tf32_split(w1s[hrow * 68 + k0 + 4], bh1, bl1);
#pragma unroll
                    for (int m = 0; m < 2; m++) {
                        mma_16n8k8(acc[m][nt], ahi[m], bh0, bh1);
                        mma_16n8k8(acc[m][nt], alo[m], bh0, bh1);
                        mma_16n8k8(acc[m][nt], ahi[m], bl0, bl1);
                    }
                }
            }

            // D -> relu(+b1) -> hbuf
#pragma unroll
            for (int m = 0; m < 2; m++) {
                const int p0 = g4 + 16 * m;
#pragma unroll
                for (int nt = 0; nt < 8; nt++) {
                    const int col = nt * 8 + 2 * t4;
                    hb[p0 * 68 + col]           = fmaxf(acc[m][nt][0] + b1s[hc + col], 0.f);
                    hb[p0 * 68 + col + 1]       = fmaxf(acc[m][nt][1] + b1s[hc + col + 1], 0.f);
                    hb[(p0 + 8) * 68 + col]     = fmaxf(acc[m][nt][2] + b1s[hc + col], 0.f);
                    hb[(p0 + 8) * 68 + col + 1] = fmaxf(acc[m][nt][3] + b1s[hc + col + 1], 0.f);
                }
            }
            __syncwarp();

            // layer-2 partials (scalar f32x2) over this chunk, own pixel row
            const float4* hrow4 = (const float4*)&hb[lane * 68];
#pragma unroll
            for (int j4 = 0; j4 < 16; j4++) {
                float4 hv = hrow4[j4];
                const float hvv[4] = {hv.x, hv.y, hv.z, hv.w};
#pragma unroll
                for (int s = 0; s < 4; s++) {
                    const int o = hc + j4 * 4 + s;
                    ULL hp2 = pack2(hvv[s], hvv[s]);
                    const ulonglong2* wr = (const ulonglong2*)&w2ts[o * 8];
#pragma unroll
                    for (int j = 0; j < 4; j++) {
                        ulonglong2 q = wr[j];
                        dx2[2 * j]     = fma2(q.x, hp2, dx2[2 * j]);
                        dx2[2 * j + 1] = fma2(q.y, hp2, dx2[2 * j + 1]);
                    }
                }
            }
            __syncwarp();  // hbuf reused next chunk
        }

        // ---- epilogue: x_new = x + dx ----
#pragma unroll
        for (int j = 0; j < 8; j++) {
            float d0, d1;
            unpack2(d0, d1, dx2[j]);
            const int ch0 = 2 * j, ch1 = 2 * j + 1;
            float xn0 = cen[ch0] + d0;
            float xn1 = cen[ch1] + d1;
            out[(size_t)(b * 16 + ch0) * HW + pid] = xn0;
            out[(size_t)(b * 16 + ch1) * HW + pid] = xn1;
            if (j == 1) g_alpha[(size_t)b * HW + pid] = xn1;
        }
        __syncwarp();  // ybuf reused next iteration
    }
}

__global__ void __launch_bounds__(256) nca_life_kernel(
    const float* __restrict__ x, float* __restrict__ out)
{
    const int w = threadIdx.x;
    const int h = blockIdx.x;
    const int b = blockIdx.y;
    const int pid = h * 256 + w;
    const float* x3 = x + (size_t)(b * 16 + 3) * HW;
    const float* al = g_alpha + (size_t)b * HW;

    float pre = -1e30f, post = -1e30f;
#pragma unroll
    for (int dh = -1; dh <= 1; dh++) {
        int hh = h + dh;
        if (hh < 0 || hh > 255) continue;
#pragma unroll
        for (int dw = -1; dw <= 1; dw++) {
            int ww = w + dw;
            if (ww < 0 || ww > 255) continue;
            int q = hh * 256 + ww;
            pre  = fmaxf(pre,  __ldg(x3 + q));
            post = fmaxf(post, al[q]);
        }
    }
    if (!(pre > 0.1f && post > 0.1f)) {
#pragma unroll
        for (int c = 0; c < 16; c++)
            out[(size_t)(b * 16 + c) * HW + pid] = 0.f;
    }
}

extern "C" void kernel_launch(void* const* d_in, const int* in_sizes, int n_in,
                              void* d_out, int out_size)
{
    const float* x  = nullptr; const float* rm = nullptr;
    const float* w1 = nullptr; const float* b1 = nullptr; const float* w2 = nullptr;
    for (int i = 0; i < n_in; i++) {
        switch (in_sizes[i]) {
            case 16777216: x  = (const float*)d_in[i]; break;
            case 1048576:  rm = (const float*)d_in[i]; break;
            case 8192:     w1 = (const float*)d_in[i]; break;
            case 2048:     w2 = (const float*)d_in[i]; break;
            case 128:      b1 = (const float*)d_in[i]; break;
            default: break;
        }
    }
    if (!x || !rm || !w1 || !b1 || !w2) return;
    float* out = (float*)d_out;

    cudaFuncSetAttribute(nca_mlp_kernel,
                         cudaFuncAttributeMaxDynamicSharedMemorySize, SMEM_TOTAL);

    dim3 grid(256, 16);
    nca_zero_kernel<<<1, 1>>>();
    nca_prep_kernel<<<grid, 256>>>(x, rm, out);
    nca_mlp_kernel<<<MLP_BLOCKS, MLP_THREADS, SMEM_TOTAL>>>(x, w1, b1, w2, out);
    nca_life_kernel<<<grid, 256>>>(x, out);
}

// round 14
// speedup vs baseline: 1.2933x; 1.2933x over previous
#include <cuda_runtime.h>
#include <cstdint>

// NCA grow step — fire-sparsity compaction + persistent MLP with L1 prefetch.
// (Restored R11 — measured best at 430.7us. Tensor paths closed by evidence:
//  tcgen05 rejected by compute_100 ptxas (R6); legacy mma.sync tf32 3-term
//  split measured 560us (R13) — legacy HMMA is de-rated on sm_100.)
//
//  zero:  reset compaction counter (graph-replay safe).
//  prep:  fire = rand_mask <= 0.5. Non-fired pixels: x_new = x -> out + alpha.
//         Fired pixels: ballot-compacted into g_list (~50% of 1M).
//  mlp:   persistent (296 blocks, 2/SM): grid-stride over g_list, FULL warps.
//         Prefetches the NEXT pixel's 3x3 stencil rows into L1 during the
//         current pixel's MLP to hide scattered-load latency.
//  life:  life = (maxpool3(x.a)>0.1)&(maxpool3(x_new.a)>0.1); zero dead pixels.

typedef unsigned long long ULL;

#define HW 65536  // 256*256

__device__ float g_alpha[16 * HW];   // x_new alpha scratch (4 MB)
__device__ int   g_list[16 * HW];    // fired pixel ids: b*65536 + pid (4 MB)
__device__ int   g_count;

__device__ __forceinline__ ULL pack2(float lo, float hi) {
    ULL r;
    asm("mov.b64 %0, {%1, %2};" : "=l"(r) : "f"(lo), "f"(hi));
    return r;
}
__device__ __forceinline__ void unpack2(float& lo, float& hi, ULL v) {
    asm("mov.b64 {%0, %1}, %2;" : "=f"(lo), "=f"(hi) : "l"(v));
}
__device__ __forceinline__ ULL fma2(ULL a, ULL b, ULL c) {
    ULL d;
    asm("fma.rn.f32x2 %0, %1, %2, %3;" : "=l"(d) : "l"(a), "l"(b), "l"(c));
    return d;
}
__device__ __forceinline__ ULL add2(ULL a, ULL b) {
    ULL d;
    asm("add.rn.f32x2 %0, %1, %2;" : "=l"(d) : "l"(a), "l"(b));
    return d;
}
__device__ __forceinline__ void pf_l1(const void* p) {
    asm volatile("prefetch.global.L1 [%0];" :: "l"(p));
}

__global__ void nca_zero_kernel() { g_count = 0; }

// ---- prep: handle non-fired pixels, compact fired pixel ids ----
__global__ void __launch_bounds__(256) nca_prep_kernel(
    const float* __restrict__ x, const float* __restrict__ rmask,
    float* __restrict__ out)
{
    const int w = threadIdx.x;
    const int h = blockIdx.x;
    const int b = blockIdx.y;
    const int pid = h * 256 + w;
    const int lane = w & 31;

    const bool fire = __ldg(rmask + (size_t)b * HW + pid) <= 0.5f;

    unsigned m = __ballot_sync(0xffffffffu, fire);
    int base = 0;
    if (lane == 0) base = atomicAdd(&g_count, __popc(m));
    base = __shfl_sync(0xffffffffu, base, 0);
    if (fire) {
        g_list[base + __popc(m & ((1u << lane) - 1u))] = b * HW + pid;
    } else {
        // x_new = x: copy through, record alpha
#pragma unroll
        for (int c = 0; c < 16; c++) {
            float v = __ldg(x + (size_t)(b * 16 + c) * HW + pid);
            out[(size_t)(b * 16 + c) * HW + pid] = v;
            if (c == 3) g_alpha[(size_t)b * HW + pid] = v;
        }
    }
}

// ---- mlp: persistent full-warp work on fired pixels only ----
#define MLP_BLOCKS 296  // 2 CTAs/SM x 148 SMs

__global__ void __launch_bounds__(256, 2) nca_mlp_kernel(
    const float* __restrict__ x,
    const float* __restrict__ w1, const float* __restrict__ b1,
    const float* __restrict__ w2, float* __restrict__ out)
{
    __shared__ __align__(16) ULL w1s[4096];   // [128 o][32 pairs of i]  (32 KB)
    __shared__ __align__(16) ULL w2ts[1024];  // [128 o][8 pairs of out-c] (8 KB)
    __shared__ float b1s[128];

    const int tid = threadIdx.x;

    const ULL* w1u = reinterpret_cast<const ULL*>(w1);
    for (int i = tid; i < 4096; i += 256) w1s[i] = w1u[i];
    if (tid < 128) b1s[tid] = b1[tid];
    for (int i = tid; i < 1024; i += 256) {
        int o = i >> 3, j = i & 7;
        w2ts[i] = pack2(w2[(2 * j) * 128 + o], w2[(2 * j + 1) * 128 + o]);
    }
    __syncthreads();

    const int count = g_count;
    const int stride = MLP_BLOCKS * 256;

    for (int idx = blockIdx.x * 256 + tid; idx < count; idx += stride) {
        const int p = __ldg(&g_list[idx]);
        const int b = p >> 16;
        const int pid = p & 0xFFFF;
        const int h = pid >> 8;
        const int w = pid & 255;
        const bool hm = h > 0, hp = h < 255, wm = w > 0, wp = w < 255;

        // ---- Perceive: y[64] as 32 x f32x2: (id,sx),(sy,lap) per channel ----
        ULL y2[32];
#pragma unroll
        for (int c = 0; c < 16; c++) {
            const float* xc = x + (size_t)(b * 16 + c) * HW + pid;
            float v00 = (hm && wm) ? __ldg(xc - 257) : 0.f;
            float v01 = hm         ? __ldg(xc - 256) : 0.f;
            float v02 = (hm && wp) ? __ldg(xc - 255) : 0.f;
            float v10 = wm         ? __ldg(xc - 1)   : 0.f;
            float v11 =              __ldg(xc);
            float v12 = wp         ? __ldg(xc + 1)   : 0.f;
            float v20 = (hp && wm) ? __ldg(xc + 255) : 0.f;
            float v21 = hp         ? __ldg(xc + 256) : 0.f;
            float v22 = (hp && wp) ? __ldg(xc + 257) : 0.f;
            float sx  = ((v02 - v00) + 2.f * (v12 - v10) + (v22 - v20)) * 0.125f;
            float sy  = ((v20 - v00) + 2.f * (v21 - v01) + (v22 - v02)) * 0.125f;
            float lap = v01 + v10 + v12 + v21 - 4.f * v11;
            y2[2 * c]     = pack2(v11, sx);
            y2[2 * c + 1] = pack2(sy, lap);
        }

        // ---- Prefetch next pixel's stencil rows into L1 (hidden under MLP) ----
        const int nidx = idx + stride;
        if (nidx < count) {
            const int pn = __ldg(&g_list[nidx]);
            const int npid = pn & 0xFFFF;
            const float* xb = x + (size_t)(pn >> 16) * 16 * HW + npid;
            const int up = (npid >= 256) ? -256 : 0;
            const int dn = (npid < HW - 256) ? 256 : 0;
#pragma unroll
            for (int c = 0; c < 16; c++) {
                const float* r = xb + (size_t)c * HW;
                pf_l1(r + up);
                pf_l1(r);
                pf_l1(r + dn);
            }
        }

        // ---- MLP: 64 -> 128 (relu) -> 16 ----
        ULL dx2[8];
#pragma unroll
        for (int j = 0; j < 8; j++) dx2[j] = 0ULL;

#pragma unroll 2
        for (int o = 0; o < 128; o++) {
            const ulonglong2* row = reinterpret_cast<const ulonglong2*>(&w1s[o * 32]);
            ULL a0 = 0ULL, a1 = 0ULL, a2 = 0ULL, a3 = 0ULL;
#pragma unroll
            for (int i = 0; i < 8; i++) {
                ulonglong2 q0 = row[2 * i];
                ulonglong2 q1 = row[2 * i + 1];
                a0 = fma2(q0.x, y2[4 * i + 0], a0);
                a1 = fma2(q0.y, y2[4 * i + 1], a1);
                a2 = fma2(q1.x, y2[4 * i + 2], a2);
                a3 = fma2(q1.y, y2[4 * i + 3], a3);
            }
            ULL s = add2(add2(a0, a1), add2(a2, a3));
            float slo, shi;
            unpack2(slo, shi, s);
            float hv = fmaxf(slo + shi + b1s[o], 0.f);
            ULL hp2 = pack2(hv, hv);
            const ulonglong2* wr = reinterpret_cast<const ulonglong2*>(&w2ts[o * 8]);
#pragma unroll
            for (int j = 0; j < 4; j++) {
                ulonglong2 q = wr[j];
                dx2[2 * j]     = fma2(q.x, hp2, dx2[2 * j]);
                dx2[2 * j + 1] = fma2(q.y, hp2, dx2[2 * j + 1]);
            }
        }

        // ---- x_new = x + dx (fire==1 for all listed pixels) ----
#pragma unroll
        for (int j = 0; j < 8; j++) {
            float d0, d1;
            unpack2(d0, d1, dx2[j]);
            int ch0 = 2 * j, ch1 = 2 * j + 1;
            float cen0, cen1, t;
            unpack2(cen0, t, y2[2 * ch0]);  // identity filter = center value
            unpack2(cen1, t, y2[2 * ch1]);
            float xn0 = cen0 + d0;
            float xn1 = cen1 + d1;
            out[(size_t)(b * 16 + ch0) * HW + pid] = xn0;
            out[(size_t)(b * 16 + ch1) * HW + pid] = xn1;
            if (j == 1)  // ch1 == 3: alpha
                g_alpha[(size_t)b * HW + pid] = xn1;
        }
    }
}

__global__ void __launch_bounds__(256) nca_life_kernel(
    const float* __restrict__ x, float* __restrict__ out)
{
    const int w = threadIdx.x;
    const int h = blockIdx.x;
    const int b = blockIdx.y;
    const int pid = h * 256 + w;

    const float* x3 = x + (size_t)(b * 16 + 3) * HW;
    const float* al = g_alpha + (size_t)b * HW;

    float pre = -1e30f, post = -1e30f;
#pragma unroll
    for (int dh = -1; dh <= 1; dh++) {
        int hh = h + dh;
        if (hh < 0 || hh > 255) continue;
#pragma unroll
        for (int dw = -1; dw <= 1; dw++) {
            int ww = w + dw;
            if (ww < 0 || ww > 255) continue;
            int q = hh * 256 + ww;
            pre  = fmaxf(pre,  __ldg(x3 + q));
            post = fmaxf(post, al[q]);
        }
    }

    if (!(pre > 0.1f && post > 0.1f)) {
#pragma unroll
        for (int c = 0; c < 16; c++)
            out[(size_t)(b * 16 + c) * HW + pid] = 0.f;
    }
}

extern "C" void kernel_launch(void* const* d_in, const int* in_sizes, int n_in,
                              void* d_out, int out_size)
{
    // Bind inputs by element count — all five distinct.
    const float* x  = nullptr; const float* rm = nullptr;
    const float* w1 = nullptr; const float* b1 = nullptr; const float* w2 = nullptr;
    for (int i = 0; i < n_in; i++) {
        switch (in_sizes[i]) {
            case 16777216: x  = (const float*)d_in[i]; break;
            case 1048576:  rm = (const float*)d_in[i]; break;
            case 8192:     w1 = (const float*)d_in[i]; break;
            case 2048:     w2 = (const float*)d_in[i]; break;
            case 128:      b1 = (const float*)d_in[i]; break;
            default: break;
        }
    }
    if (!x || !rm || !w1 || !b1 || !w2) return;
    float* out = (float*)d_out;

    dim3 grid(256, 16);
    nca_zero_kernel<<<1, 1>>>();
    nca_prep_kernel<<<grid, 256>>>(x, rm, out);
    nca_mlp_kernel<<<MLP_BLOCKS, 256>>>(x, w1, b1, w2, out);
    nca_life_kernel<<<grid, 256>>>(x, out);
}